// round 1
// baseline (speedup 1.0000x reference)
#include <cuda_runtime.h>

// KAN 1-D conv: out[b,o,w] = sum_{i,k} silu(x[b,i,w+k])*base_w[o,i,k]
//                          + sum_{i,k,c} B3_c(x[b,i,w+k]) * spline_w[o,i,k,c]*scaler[o,i,k]
// B=32, I=8, O=32, W=8192, K=5, Wo=8188, 8 cubic B-spline bases (G=5, SO=3).

#define B_DIM 32
#define I_DIM 8
#define O_DIM 32
#define W_IN 8192
#define KSZ 5
#define W_OUT (W_IN - KSZ + 1)   // 8188
#define NC 9                      // 1 silu + 8 spline bases
#define TILE_W 128
#define FP (TILE_W + KSZ - 1)     // 132 feature positions per tile
#define NTHREADS 128
#define NTILES ((W_OUT + TILE_W - 1) / TILE_W)   // 64

// grid knot value, matches GRID = arange(-3, 9)*(2/5) - 1 in fp32
__host__ __device__ constexpr float gridc(int j) {
    return (float)(j - 3) * 0.4f - 1.0f;
}

// Wc smem: [I][K][NC][O]  (o contiguous for float4 loads)
#define WC_ELEMS (I_DIM * KSZ * NC * O_DIM)      // 11520
// Fs smem: [I][NC][FP]
#define FS_ELEMS (I_DIM * NC * FP)               // 9504
#define SMEM_FLOATS (WC_ELEMS + FS_ELEMS)        // 21024 -> 84096 bytes

__global__ __launch_bounds__(NTHREADS)
void kan_conv1d_kernel(const float* __restrict__ x,
                       const float* __restrict__ base_weight,
                       const float* __restrict__ spline_weight,
                       const float* __restrict__ spline_scaler,
                       float* __restrict__ out)
{
    extern __shared__ float smem[];
    float* Wc = smem;                 // [I][K][NC][O]
    float* Fs = smem + WC_ELEMS;      // [I][NC][FP]

    const int tid = threadIdx.x;
    const int b   = blockIdx.y;
    const int w0  = blockIdx.x * TILE_W;

    // ---- Phase 1: fuse weights into smem ----
    // idx enumerates (o,i,k) in the global (O,I,K) row-major order.
    for (int idx = tid; idx < O_DIM * I_DIM * KSZ; idx += NTHREADS) {
        int k = idx % KSZ;
        int r = idx / KSZ;
        int i = r % I_DIM;
        int o = r / I_DIM;
        float bw = base_weight[idx];
        float sc = spline_scaler[idx];
        float* dst = &Wc[((i * KSZ + k) * NC) * O_DIM + o];
        dst[0] = bw;
        const float* sw = &spline_weight[idx * 8];
        #pragma unroll
        for (int c = 0; c < 8; c++)
            dst[(c + 1) * O_DIM] = sw[c] * sc;
    }

    // ---- Phase 2: per-element features (silu + 8 cubic B-spline bases) ----
    for (int e = tid; e < I_DIM * FP; e += NTHREADS) {
        int i = e / FP;
        int p = e % FP;
        int gw = w0 + p;
        float xv = (gw < W_IN) ? x[(b * I_DIM + i) * W_IN + gw] : 0.0f;

        float* f = &Fs[i * NC * FP + p];
        // silu
        f[0] = xv / (1.0f + __expf(-xv));

        // Cox-de-Boor, degree 0..3 on uniform grid (knot spans constant-folded)
        float b0[11];
        #pragma unroll
        for (int j = 0; j < 11; j++)
            b0[j] = (xv >= gridc(j) && xv < gridc(j + 1)) ? 1.0f : 0.0f;

        float b1[10];
        #pragma unroll
        for (int j = 0; j < 10; j++) {
            float l = (xv - gridc(j))     * (1.0f / (gridc(j + 1) - gridc(j)));
            float r = (gridc(j + 2) - xv) * (1.0f / (gridc(j + 2) - gridc(j + 1)));
            b1[j] = l * b0[j] + r * b0[j + 1];
        }
        float b2[9];
        #pragma unroll
        for (int j = 0; j < 9; j++) {
            float l = (xv - gridc(j))     * (1.0f / (gridc(j + 2) - gridc(j)));
            float r = (gridc(j + 3) - xv) * (1.0f / (gridc(j + 3) - gridc(j + 1)));
            b2[j] = l * b1[j] + r * b1[j + 1];
        }
        #pragma unroll
        for (int j = 0; j < 8; j++) {
            float l = (xv - gridc(j))     * (1.0f / (gridc(j + 3) - gridc(j)));
            float r = (gridc(j + 4) - xv) * (1.0f / (gridc(j + 4) - gridc(j + 1)));
            f[(j + 1) * FP] = l * b2[j] + r * b2[j + 1];
        }
    }
    __syncthreads();

    // ---- Phase 3: register-blocked MAC, 4 o x 8 w per thread ----
    const int wt = tid & 15;     // 16 w-lanes
    const int og = tid >> 4;     // 8 o-groups
    const int o0 = og * 4;

    float acc[4][8];
    #pragma unroll
    for (int oo = 0; oo < 4; oo++)
        #pragma unroll
        for (int ww = 0; ww < 8; ww++)
            acc[oo][ww] = 0.0f;

    const float* fbase = Fs + wt;

    #pragma unroll 1
    for (int i = 0; i < I_DIM; i++) {
        #pragma unroll 1
        for (int k = 0; k < KSZ; k++) {
            const float*  fptr = fbase + i * (NC * FP) + k;
            const float4* wptr = (const float4*)&Wc[((i * KSZ + k) * NC) * O_DIM + o0];
            #pragma unroll
            for (int c = 0; c < NC; c++) {
                float4 wv = wptr[c * (O_DIM / 4)];
                float fv[8];
                #pragma unroll
                for (int ww = 0; ww < 8; ww++)
                    fv[ww] = fptr[c * FP + 16 * ww];
                #pragma unroll
                for (int ww = 0; ww < 8; ww++) {
                    acc[0][ww] += wv.x * fv[ww];
                    acc[1][ww] += wv.y * fv[ww];
                    acc[2][ww] += wv.z * fv[ww];
                    acc[3][ww] += wv.w * fv[ww];
                }
            }
        }
    }

    // ---- Phase 4: store ----
    #pragma unroll
    for (int oo = 0; oo < 4; oo++) {
        float* orow = out + ((size_t)(b * O_DIM + o0 + oo)) * W_OUT + w0 + wt;
        #pragma unroll
        for (int ww = 0; ww < 8; ww++) {
            int w = w0 + wt + 16 * ww;
            if (w < W_OUT) orow[16 * ww] = acc[oo][ww];
        }
    }
}

extern "C" void kernel_launch(void* const* d_in, const int* in_sizes, int n_in,
                              void* d_out, int out_size)
{
    const float* x             = (const float*)d_in[0];
    const float* base_weight   = (const float*)d_in[1];
    const float* spline_weight = (const float*)d_in[2];
    const float* spline_scaler = (const float*)d_in[3];
    float* out = (float*)d_out;

    size_t smem_bytes = SMEM_FLOATS * sizeof(float);   // 84096
    cudaFuncSetAttribute(kan_conv1d_kernel,
                         cudaFuncAttributeMaxDynamicSharedMemorySize,
                         (int)smem_bytes);

    dim3 grid(NTILES, B_DIM);   // 64 x 32
    kan_conv1d_kernel<<<grid, NTHREADS, smem_bytes>>>(
        x, base_weight, spline_weight, spline_scaler, out);
}